// round 3
// baseline (speedup 1.0000x reference)
#include <cuda_runtime.h>
#include <math.h>
#include <stdint.h>

#define N_RNA 4096
#define N_ATAC 8192
#define IN_C 256
#define HID 128
#define THR_S 0.8f

// ---------------- scratch (static device memory; no allocations) ----------------
__device__ float g_Q[N_RNA * HID];
__device__ float g_K[N_ATAC * HID];
__device__ float g_VR[N_RNA * HID];
__device__ float g_VA[N_ATAC * HID];
__device__ float g_AGGR[N_RNA * HID];
__device__ float g_AGGA[N_ATAC * HID];
__device__ float g_CR[N_RNA * 2 * HID];
__device__ float g_CA[N_ATAC * 2 * HID];

// ---------------- batched GEMM: C[m, coff + 0..127] = A[M,K] @ W[K,128] + b ----------------
struct GemmOp {
    const float* A;
    const float* W;
    const float* B;
    float* C;
    int M;
    int K;
    int ldc;
    int coff;
};
struct GemmBatch { GemmOp op[6]; };

__global__ void __launch_bounds__(256) gemm_kernel(GemmBatch batch) {
    const GemmOp op = batch.op[blockIdx.y];
    const int m0 = blockIdx.x * 64;
    if (m0 >= op.M) return;

    __shared__ float a_s[64][33];
    __shared__ float w_s[32][128];

    float acc[8][4];
#pragma unroll
    for (int i = 0; i < 8; ++i) {
        acc[i][0] = 0.f; acc[i][1] = 0.f; acc[i][2] = 0.f; acc[i][3] = 0.f;
    }

    const int t = threadIdx.x;
    const float4* A4 = (const float4*)op.A;
    const float4* W4 = (const float4*)op.W;
    const int Kd4 = op.K >> 2;

    for (int kk = 0; kk < op.K; kk += 32) {
        __syncthreads();
        {
            int k4 = t & 7, r = t >> 3;
#pragma unroll
            for (int rr = 0; rr < 2; ++rr) {
                float4 v = A4[(size_t)(m0 + r + rr * 32) * Kd4 + (kk >> 2) + k4];
                a_s[r + rr * 32][k4 * 4 + 0] = v.x;
                a_s[r + rr * 32][k4 * 4 + 1] = v.y;
                a_s[r + rr * 32][k4 * 4 + 2] = v.z;
                a_s[r + rr * 32][k4 * 4 + 3] = v.w;
            }
        }
        {
#pragma unroll
            for (int p = 0; p < 4; ++p) {
                int idx = t + p * 256;
                int k = idx >> 5, c4 = idx & 31;
                *(float4*)&w_s[k][c4 * 4] = W4[(size_t)(kk + k) * 32 + c4];
            }
        }
        __syncthreads();
#pragma unroll
        for (int k = 0; k < 32; ++k) {
            float4 w4 = *(const float4*)&w_s[k][(t & 31) * 4];
#pragma unroll
            for (int i = 0; i < 8; ++i) {
                float av = a_s[(t >> 5) * 8 + i][k];
                acc[i][0] += av * w4.x;
                acc[i][1] += av * w4.y;
                acc[i][2] += av * w4.z;
                acc[i][3] += av * w4.w;
            }
        }
    }

    const int c = (t & 31) * 4;
    const int rb = (t >> 5) * 8;
    float4 b4 = *(const float4*)&op.B[c];
#pragma unroll
    for (int i = 0; i < 8; ++i) {
        size_t row = (size_t)(m0 + rb + i);
        float4 o;
        o.x = acc[i][0] + b4.x;
        o.y = acc[i][1] + b4.y;
        o.z = acc[i][2] + b4.z;
        o.w = acc[i][3] + b4.w;
        *(float4*)&op.C[row * op.ldc + op.coff + c] = o;
    }
}

// ---------------- cp.async helpers ----------------
__device__ __forceinline__ void cp_async16(uint32_t dst, const void* src) {
    asm volatile("cp.async.cg.shared.global [%0], [%1], 16;" :: "r"(dst), "l"(src));
}
__device__ __forceinline__ void cp_commit() { asm volatile("cp.async.commit_group;"); }
__device__ __forceinline__ void cp_wait1() { asm volatile("cp.async.wait_group 1;"); }

// ---------------- top-k helpers ----------------
__device__ __forceinline__ bool tk_better(float v, int i, float v2, int i2) {
    return (v > v2) || (v == v2 && i < i2);
}

// full-comparator insert (merge phase)
__device__ __forceinline__ void tk_insert(float* bv, int* bi, float v, int gi) {
    bool done = false;
#pragma unroll
    for (int k = 9; k > 0; --k) {
        if (!done) {
            if (tk_better(v, gi, bv[k - 1], bi[k - 1])) {
                bv[k] = bv[k - 1];
                bi[k] = bi[k - 1];
            } else {
                bv[k] = v;
                bi[k] = gi;
                done = true;
            }
        }
    }
    if (!done) { bv[0] = v; bi[0] = gi; }
}

// value-only insert: valid when candidate indices arrive in ascending order
// (ties must lose to the already-present lower index -> strict >)
__device__ __forceinline__ void tk_insert_v(float* bv, int* bi, float v, int gi) {
    bool done = false;
#pragma unroll
    for (int k = 9; k > 0; --k) {
        if (!done) {
            if (v > bv[k - 1]) {
                bv[k] = bv[k - 1];
                bi[k] = bi[k - 1];
            } else {
                bv[k] = v;
                bi[k] = gi;
                done = true;
            }
        }
    }
    if (!done) { bv[0] = v; bi[0] = gi; }
}

// ---------------- fused attention v2: cp.async double-buffered K/mask ----------------
// Tile: 16 rna rows x 2 heads per block (grid 256), a streamed in chunks of 128.
// Dynamic smem layout (174080 B, 1 block/SM):
//   q_s : float4[32][17]            @ 0       (8704 B)
//   k0  : float4[32][129]           @ 8704    (66048 B)
//   k1  : float4[32][129]           @ 74752   (66048 B)
//   m0  : float[16][128]            @ 140800  (8192 B)
//   m1  : float[16][128]            @ 148992  (8192 B)
//   l_s : float[32][132]            @ 157184  (16896 B)
// topk merge buffers overlay m0/m1 after the main loop.
#define SM_Q  0
#define SM_K0 8704
#define SM_K1 74752
#define SM_M0 140800
#define SM_M1 148992
#define SM_L  157184
#define SM_TOTAL 174080

__global__ void __launch_bounds__(128) attn_kernel(const float* __restrict__ mask) {
    extern __shared__ char smraw[];
    const uint32_t sbase = (uint32_t)__cvta_generic_to_shared(smraw);
    float4* q_s = (float4*)(smraw + SM_Q);
    float* l_s = (float*)(smraw + SM_L);
    float4* const kb0 = (float4*)(smraw + SM_K0);
    float4* const kb1 = (float4*)(smraw + SM_K1);
    float* const mb0 = (float*)(smraw + SM_M0);
    float* const mb1 = (float*)(smraw + SM_M1);

    const int t = threadIdx.x;
    const int r0 = blockIdx.x * 16;

    const int ag = t & 15;          // a-lane (compute)
    const int hh = (t >> 4) & 1;    // head (compute)
    const int rg = t >> 5;          // r-group (compute)
    const int row = t & 31;         // row = r_local*2 + h (scan)
    const int sub = t >> 5;         // a-quarter (scan)

    const float4* K4 = (const float4*)g_K;
    const float4* M4 = (const float4*)mask;
    const int sd4 = t & 31;         // staging lane
    const int sal = t >> 5;

    // ---- stage helper (macro-ish lambda) ----
    auto stage = [&](int c, int p) {
        const int a0 = c * 128;
        uint32_t kdst = sbase + (p ? SM_K1 : SM_K0);
#pragma unroll 8
        for (int j = 0; j < 32; ++j) {
            int a = sal + j * 4;
            cp_async16(kdst + (uint32_t)(sd4 * 129 + a) * 16,
                       K4 + (size_t)(a0 + a) * 32 + sd4);
        }
        uint32_t mdst = sbase + (p ? SM_M1 : SM_M0);
#pragma unroll
        for (int j = 0; j < 4; ++j) {
            int e = t + 128 * j;
            int rr = e >> 5, c4 = e & 31;
            cp_async16(mdst + (uint32_t)(rr * 32 + c4) * 16,
                       M4 + (size_t)(r0 + rr) * 2048 + (a0 >> 2) + c4);
        }
    };

    // load Q tile, d4-major (plain loads, one time)
    {
        int d4 = t & 31, rl = t >> 5;
        const float4* Q4 = (const float4*)g_Q;
#pragma unroll
        for (int j = 0; j < 4; ++j) {
            int r = rl + j * 4;
            q_s[d4 * 17 + r] = Q4[(size_t)(r0 + r) * 32 + d4];
        }
    }

    // prologue: prefetch chunks 0 and 1
    stage(0, 0); cp_commit();
    stage(1, 1); cp_commit();

    float bv[10];
    int bi[10];
#pragma unroll
    for (int k = 0; k < 10; ++k) { bv[k] = -1e30f; bi[k] = 0x7fffffff; }

    for (int c = 0; c < N_ATAC / 128; ++c) {
        const int p = c & 1;
        const int a0 = c * 128;
        const float4* kp = p ? kb1 : kb0;
        const float* mp = p ? mb1 : mb0;

        cp_wait1();        // chunk c data landed (chunk c+1 may still fly)
        __syncthreads();   // visible to all; l_s free (prev scan done)

        // ---- compute 4r x 8a logits per thread (one head) ----
        float acc[4][8];
#pragma unroll
        for (int i = 0; i < 4; ++i)
#pragma unroll
            for (int j = 0; j < 8; ++j) acc[i][j] = 0.f;

#pragma unroll
        for (int dd = 0; dd < 16; ++dd) {
            int d4 = hh * 16 + dd;
            float4 kf[8];
#pragma unroll
            for (int j = 0; j < 8; ++j) kf[j] = kp[d4 * 129 + ag + j * 16];
#pragma unroll
            for (int i = 0; i < 4; ++i) {
                float4 qf = q_s[d4 * 17 + rg * 4 + i];
#pragma unroll
                for (int j = 0; j < 8; ++j) {
                    acc[i][j] += qf.x * kf[j].x;
                    acc[i][j] += qf.y * kf[j].y;
                    acc[i][j] += qf.z * kf[j].z;
                    acc[i][j] += qf.w * kf[j].w;
                }
            }
        }

        // masked logits to l_s (sigmoid monotone -> rank on logits)
#pragma unroll
        for (int i = 0; i < 4; ++i) {
            int r = rg * 4 + i;
#pragma unroll
            for (int j = 0; j < 8; ++j) {
                int a = ag + j * 16;
                l_s[(r * 2 + hh) * 132 + a] = acc[i][j] * mp[r * 128 + a];
            }
        }
        __syncthreads();   // all reads of k[p]/m[p] and writes of l_s done

        // prefetch chunk c+2 into buffer p (now free)
        if (c + 2 < N_ATAC / 128) stage(c + 2, p);
        cp_commit();       // commit (possibly empty) to keep group count aligned

        // ---- top-k scan: 32 a's per thread, float4 + max filter ----
        {
            const float4* lp = (const float4*)(l_s + row * 132 + sub * 32);
            const int gibase = a0 + sub * 32;
#pragma unroll
            for (int ii = 0; ii < 8; ++ii) {
                float4 v = lp[ii];
                float mx = fmaxf(fmaxf(v.x, v.y), fmaxf(v.z, v.w));
                if (mx > bv[9]) {
                    int gi = gibase + ii * 4;
                    if (v.x > bv[9]) tk_insert_v(bv, bi, v.x, gi);
                    if (v.y > bv[9]) tk_insert_v(bv, bi, v.y, gi + 1);
                    if (v.z > bv[9]) tk_insert_v(bv, bi, v.z, gi + 2);
                    if (v.w > bv[9]) tk_insert_v(bv, bi, v.w, gi + 3);
                }
            }
        }
    }

    __syncthreads();  // all scans done; m buffers dead -> overlay

    float* tv = mb0;                 // [32*4*10] floats   (5120 B)
    int* ti = (int*)(mb0 + 1280);    // [32*4*10] ints     (5120 B)
    float* wv = mb0 + 2560;          // [32*10]            (1280 B)
    int* wi = (int*)(mb0 + 2880);    // [32*10]            (1280 B)

#pragma unroll
    for (int k = 0; k < 10; ++k) {
        tv[(row * 4 + sub) * 10 + k] = bv[k];
        ti[(row * 4 + sub) * 10 + k] = bi[k];
    }
    __syncthreads();

    // merge 4 partial lists per row -> sigmoid/softmax/threshold weights
    if (t < 32) {
        float fv[10];
        int fi[10];
#pragma unroll
        for (int k = 0; k < 10; ++k) { fv[k] = -1e30f; fi[k] = 0x7fffffff; }
        for (int s = 0; s < 4; ++s)
            for (int k = 0; k < 10; ++k) {
                float v = tv[(t * 4 + s) * 10 + k];
                int gi = ti[(t * 4 + s) * 10 + k];
                if (tk_better(v, gi, fv[9], fi[9])) tk_insert(fv, fi, v, gi);
            }
        float sig[10];
#pragma unroll
        for (int k = 0; k < 10; ++k) sig[k] = 1.f / (1.f + expf(-fv[k]));
        float e[10];
        float den = 0.f;
#pragma unroll
        for (int k = 0; k < 10; ++k) { e[k] = expf(sig[k] - sig[0]); den += e[k]; }
        float inv = 1.f / den;
#pragma unroll
        for (int k = 0; k < 10; ++k) {
            float w = e[k] * inv;
            if (!(sig[k] > THR_S)) w = 0.f;
            wv[t * 10 + k] = w;
            wi[t * 10 + k] = fi[k];
        }
    }
    __syncthreads();

    // sparse aggregation: rna gather (direct) + atac scatter (atomic)
    {
        int d = t & 63, g = t >> 6;
        for (int rr = g; rr < 32; rr += 2) {
            int rloc = rr >> 1, h = rr & 1;
            int r = r0 + rloc;
            float vr = g_VR[(size_t)r * 128 + h * 64 + d];
            float accO = 0.f;
#pragma unroll
            for (int k = 0; k < 10; ++k) {
                float w = wv[rr * 10 + k];
                int a = wi[rr * 10 + k];
                if (w != 0.f) {
                    accO += w * g_VA[(size_t)a * 128 + h * 64 + d];
                    atomicAdd(&g_AGGA[(size_t)a * 128 + h * 64 + d], w * vr);
                }
            }
            g_AGGR[(size_t)r * 128 + h * 64 + d] = accO;
        }
    }
}

// ---------------- launch ----------------
extern "C" void kernel_launch(void* const* d_in, const int* in_sizes, int n_in,
                              void* d_out, int out_size) {
    const float* x_rna = (const float*)d_in[0];
    const float* x_atac = (const float*)d_in[1];
    const float* chrom_mask = (const float*)d_in[2];
    const float* Wq = (const float*)d_in[3];
    const float* bq = (const float*)d_in[4];
    const float* Wk = (const float*)d_in[5];
    const float* bk = (const float*)d_in[6];
    const float* Wvr = (const float*)d_in[7];
    const float* bvr = (const float*)d_in[8];
    const float* Wva = (const float*)d_in[9];
    const float* bva = (const float*)d_in[10];
    const float* Wor = (const float*)d_in[11];
    const float* bor = (const float*)d_in[12];
    const float* Woa = (const float*)d_in[13];
    const float* boa = (const float*)d_in[14];
    const float* Wsr = (const float*)d_in[15];
    const float* bsr = (const float*)d_in[16];
    const float* Wsa = (const float*)d_in[17];
    const float* bsa = (const float*)d_in[18];
    const float* Wdr = (const float*)d_in[19];
    const float* bdr = (const float*)d_in[20];
    const float* Wda = (const float*)d_in[21];
    const float* bda = (const float*)d_in[22];
    float* out = (float*)d_out;

    float *Qp, *Kp, *VRp, *VAp, *AGGRp, *AGGAp, *CRp, *CAp;
    cudaGetSymbolAddress((void**)&Qp, g_Q);
    cudaGetSymbolAddress((void**)&Kp, g_K);
    cudaGetSymbolAddress((void**)&VRp, g_VR);
    cudaGetSymbolAddress((void**)&VAp, g_VA);
    cudaGetSymbolAddress((void**)&AGGRp, g_AGGR);
    cudaGetSymbolAddress((void**)&AGGAp, g_AGGA);
    cudaGetSymbolAddress((void**)&CRp, g_CR);
    cudaGetSymbolAddress((void**)&CAp, g_CA);

    cudaMemsetAsync(AGGAp, 0, (size_t)N_ATAC * HID * sizeof(float));

    GemmBatch b1 = {};
    b1.op[0] = {x_rna, Wq, bq, Qp, N_RNA, IN_C, 128, 0};
    b1.op[1] = {x_atac, Wk, bk, Kp, N_ATAC, IN_C, 128, 0};
    b1.op[2] = {x_rna, Wvr, bvr, VRp, N_RNA, IN_C, 128, 0};
    b1.op[3] = {x_atac, Wva, bva, VAp, N_ATAC, IN_C, 128, 0};
    b1.op[4] = {x_rna, Wsr, bsr, CRp, N_RNA, IN_C, 256, 128};
    b1.op[5] = {x_atac, Wsa, bsa, CAp, N_ATAC, IN_C, 256, 128};
    gemm_kernel<<<dim3(128, 6), 256>>>(b1);

    cudaFuncSetAttribute(attn_kernel, cudaFuncAttributeMaxDynamicSharedMemorySize, SM_TOTAL);
    attn_kernel<<<N_RNA / 16, 128, SM_TOTAL>>>(chrom_mask);

    GemmBatch b2 = {};
    b2.op[0] = {AGGRp, Wor, bor, CRp, N_RNA, HID, 256, 0};
    b2.op[1] = {AGGAp, Woa, boa, CAp, N_ATAC, HID, 256, 0};
    gemm_kernel<<<dim3(128, 2), 256>>>(b2);

    GemmBatch b3 = {};
    b3.op[0] = {CRp, Wdr, bdr, out, N_RNA, 2 * HID, 128, 0};
    b3.op[1] = {CAp, Wda, bda, out + (size_t)N_RNA * HID, N_ATAC, 2 * HID, 128, 0};
    gemm_kernel<<<dim3(128, 2), 256>>>(b3);
}

// round 4
// speedup vs baseline: 1.4415x; 1.4415x over previous
#include <cuda_runtime.h>
#include <math.h>
#include <stdint.h>

#define N_RNA 4096
#define N_ATAC 8192
#define IN_C 256
#define HID 128
#define THR_S 0.8f

// ---------------- scratch (static device memory; no allocations) ----------------
__device__ float g_Q[N_RNA * HID];
__device__ float g_K[N_ATAC * HID];
__device__ float g_VR[N_RNA * HID];
__device__ float g_VA[N_ATAC * HID];
__device__ float g_AGGR[N_RNA * HID];
__device__ float g_AGGA[N_ATAC * HID];
__device__ float g_CR[N_RNA * 2 * HID];
__device__ float g_CA[N_ATAC * 2 * HID];

// ---------------- batched GEMM: C[m, coff + 0..127] = A[M,K] @ W[K,128] + b ----------------
struct GemmOp {
    const float* A;
    const float* W;
    const float* B;
    float* C;
    int M;
    int K;
    int ldc;
    int coff;
};
struct GemmBatch { GemmOp op[6]; };

__global__ void __launch_bounds__(256) gemm_kernel(GemmBatch batch) {
    const GemmOp op = batch.op[blockIdx.y];
    const int m0 = blockIdx.x * 64;
    if (m0 >= op.M) return;

    __shared__ float a_s[64][33];
    __shared__ float w_s[32][128];

    float acc[8][4];
#pragma unroll
    for (int i = 0; i < 8; ++i) {
        acc[i][0] = 0.f; acc[i][1] = 0.f; acc[i][2] = 0.f; acc[i][3] = 0.f;
    }

    const int t = threadIdx.x;
    const float4* A4 = (const float4*)op.A;
    const float4* W4 = (const float4*)op.W;
    const int Kd4 = op.K >> 2;

    for (int kk = 0; kk < op.K; kk += 32) {
        __syncthreads();
        {
            int k4 = t & 7, r = t >> 3;
#pragma unroll
            for (int rr = 0; rr < 2; ++rr) {
                float4 v = A4[(size_t)(m0 + r + rr * 32) * Kd4 + (kk >> 2) + k4];
                a_s[r + rr * 32][k4 * 4 + 0] = v.x;
                a_s[r + rr * 32][k4 * 4 + 1] = v.y;
                a_s[r + rr * 32][k4 * 4 + 2] = v.z;
                a_s[r + rr * 32][k4 * 4 + 3] = v.w;
            }
        }
        {
#pragma unroll
            for (int p = 0; p < 4; ++p) {
                int idx = t + p * 256;
                int k = idx >> 5, c4 = idx & 31;
                *(float4*)&w_s[k][c4 * 4] = W4[(size_t)(kk + k) * 32 + c4];
            }
        }
        __syncthreads();
#pragma unroll
        for (int k = 0; k < 32; ++k) {
            float4 w4 = *(const float4*)&w_s[k][(t & 31) * 4];
#pragma unroll
            for (int i = 0; i < 8; ++i) {
                float av = a_s[(t >> 5) * 8 + i][k];
                acc[i][0] += av * w4.x;
                acc[i][1] += av * w4.y;
                acc[i][2] += av * w4.z;
                acc[i][3] += av * w4.w;
            }
        }
    }

    const int c = (t & 31) * 4;
    const int rb = (t >> 5) * 8;
    float4 b4 = *(const float4*)&op.B[c];
#pragma unroll
    for (int i = 0; i < 8; ++i) {
        size_t row = (size_t)(m0 + rb + i);
        float4 o;
        o.x = acc[i][0] + b4.x;
        o.y = acc[i][1] + b4.y;
        o.z = acc[i][2] + b4.z;
        o.w = acc[i][3] + b4.w;
        *(float4*)&op.C[row * op.ldc + op.coff + c] = o;
    }
}

// ---------------- cp.async helpers ----------------
__device__ __forceinline__ void cp_async16(uint32_t dst, const void* src) {
    asm volatile("cp.async.cg.shared.global [%0], [%1], 16;" :: "r"(dst), "l"(src));
}
__device__ __forceinline__ void cp_commit() { asm volatile("cp.async.commit_group;"); }
__device__ __forceinline__ void cp_wait1() { asm volatile("cp.async.wait_group 1;"); }

// ---------------- top-k helpers ----------------
__device__ __forceinline__ bool tk_better(float v, int i, float v2, int i2) {
    return (v > v2) || (v == v2 && i < i2);
}

// full-comparator insert (merge phase)
__device__ __forceinline__ void tk_insert(float* bv, int* bi, float v, int gi) {
    bool done = false;
#pragma unroll
    for (int k = 9; k > 0; --k) {
        if (!done) {
            if (tk_better(v, gi, bv[k - 1], bi[k - 1])) {
                bv[k] = bv[k - 1];
                bi[k] = bi[k - 1];
            } else {
                bv[k] = v;
                bi[k] = gi;
                done = true;
            }
        }
    }
    if (!done) { bv[0] = v; bi[0] = gi; }
}

// value-only insert: valid when candidate indices arrive in ascending order
// (ties must lose to the already-present lower index -> strict >)
__device__ __forceinline__ void tk_insert_v(float* bv, int* bi, float v, int gi) {
    bool done = false;
#pragma unroll
    for (int k = 9; k > 0; --k) {
        if (!done) {
            if (v > bv[k - 1]) {
                bv[k] = bv[k - 1];
                bi[k] = bi[k - 1];
            } else {
                bv[k] = v;
                bi[k] = gi;
                done = true;
            }
        }
    }
    if (!done) { bv[0] = v; bi[0] = gi; }
}

// ---------------- fused attention v3: 64-a chunks, cp.async double buffer,
// ---------------- 91.8 KB smem -> 2 blocks/SM (both inter- and intra-block overlap)
// Tile: 16 rna rows x 2 heads per block (grid 256), a streamed in chunks of 64.
// Dynamic smem layout (91776 B):
//   q_s : float4[32][17]   @ 0      (8704 B)
//   k0  : float4[32][65]   @ 8704   (33280 B)
//   k1  : float4[32][65]   @ 41984  (33280 B)
//   m0  : float[16][64]    @ 75264  (4096 B)
//   m1  : float[16][64]    @ 79360  (4096 B)
//   l_s : float[32][65]    @ 83456  (8320 B)
// topk merge buffers overlay k0 after the main loop.
#define SM_Q  0
#define SM_K0 8704
#define SM_K1 41984
#define SM_M0 75264
#define SM_M1 79360
#define SM_L  83456
#define SM_TOTAL 91776
#define NCHUNK (N_ATAC / 64)

__global__ void __launch_bounds__(128) attn_kernel(const float* __restrict__ mask) {
    extern __shared__ char smraw[];
    const uint32_t sbase = (uint32_t)__cvta_generic_to_shared(smraw);
    float4* q_s = (float4*)(smraw + SM_Q);
    float* l_s = (float*)(smraw + SM_L);
    float4* const kb0 = (float4*)(smraw + SM_K0);
    float4* const kb1 = (float4*)(smraw + SM_K1);
    float* const mb0 = (float*)(smraw + SM_M0);
    float* const mb1 = (float*)(smraw + SM_M1);

    const int t = threadIdx.x;
    const int r0 = blockIdx.x * 16;

    const int ag = t & 15;          // a-lane (compute)
    const int hh = (t >> 4) & 1;    // head (compute)
    const int rg = t >> 5;          // r-group (compute)
    const int row = t & 31;         // row = r_local*2 + h (scan)
    const int sub = t >> 5;         // a-quarter (scan)

    const float4* K4 = (const float4*)g_K;
    const float4* M4 = (const float4*)mask;
    const int sd4 = t & 31;         // staging lane
    const int sal = t >> 5;

    auto stage = [&](int c, int p) {
        const int a0 = c * 64;
        uint32_t kdst = sbase + (p ? SM_K1 : SM_K0);
#pragma unroll
        for (int j = 0; j < 16; ++j) {
            int a = sal + j * 4;
            cp_async16(kdst + (uint32_t)(sd4 * 65 + a) * 16,
                       K4 + (size_t)(a0 + a) * 32 + sd4);
        }
        uint32_t mdst = sbase + (p ? SM_M1 : SM_M0);
#pragma unroll
        for (int j = 0; j < 2; ++j) {
            int e = t + 128 * j;
            int rr = e >> 4, c4 = e & 15;
            cp_async16(mdst + (uint32_t)(rr * 16 + c4) * 16,
                       M4 + (size_t)(r0 + rr) * 2048 + (a0 >> 2) + c4);
        }
    };

    // load Q tile, d4-major (one time)
    {
        int d4 = t & 31, rl = t >> 5;
        const float4* Q4 = (const float4*)g_Q;
#pragma unroll
        for (int j = 0; j < 4; ++j) {
            int r = rl + j * 4;
            q_s[d4 * 17 + r] = Q4[(size_t)(r0 + r) * 32 + d4];
        }
    }

    // prologue: prefetch chunks 0 and 1
    stage(0, 0); cp_commit();
    stage(1, 1); cp_commit();

    float bv[10];
    int bi[10];
#pragma unroll
    for (int k = 0; k < 10; ++k) { bv[k] = -1e30f; bi[k] = 0x7fffffff; }

    for (int c = 0; c < NCHUNK; ++c) {
        const int p = c & 1;
        const int a0 = c * 64;
        const float4* kp = p ? kb1 : kb0;
        const float* mp = p ? mb1 : mb0;

        cp_wait1();        // chunk c landed (chunk c+1 may still fly)
        __syncthreads();   // data visible to all; l_s free (prev scan done)

        // ---- compute 4r x 4a logits per thread (one head) ----
        float acc[4][4];
#pragma unroll
        for (int i = 0; i < 4; ++i)
#pragma unroll
            for (int j = 0; j < 4; ++j) acc[i][j] = 0.f;

#pragma unroll
        for (int dd = 0; dd < 16; ++dd) {
            int d4 = hh * 16 + dd;
            float4 kf[4];
#pragma unroll
            for (int j = 0; j < 4; ++j) kf[j] = kp[d4 * 65 + ag + j * 16];
#pragma unroll
            for (int i = 0; i < 4; ++i) {
                float4 qf = q_s[d4 * 17 + rg * 4 + i];
#pragma unroll
                for (int j = 0; j < 4; ++j) {
                    acc[i][j] += qf.x * kf[j].x;
                    acc[i][j] += qf.y * kf[j].y;
                    acc[i][j] += qf.z * kf[j].z;
                    acc[i][j] += qf.w * kf[j].w;
                }
            }
        }

        // masked logits to l_s (sigmoid monotone -> rank on logits)
#pragma unroll
        for (int i = 0; i < 4; ++i) {
            int r = rg * 4 + i;
#pragma unroll
            for (int j = 0; j < 4; ++j) {
                int a = ag + j * 16;
                l_s[(r * 2 + hh) * 65 + a] = acc[i][j] * mp[r * 64 + a];
            }
        }
        __syncthreads();   // k[p]/m[p] reads and l_s writes done

        // prefetch chunk c+2 into buffer p (now free); flies over the scan
        if (c + 2 < NCHUNK) stage(c + 2, p);
        cp_commit();       // commit (possibly empty) keeps group accounting aligned

        // ---- top-k scan: 16 a's per thread, scalar LDS + 4-wide max filter ----
        {
            const float* lp = l_s + row * 65 + sub * 16;
            const int gibase = a0 + sub * 16;
#pragma unroll
            for (int g = 0; g < 4; ++g) {
                float v0 = lp[g * 4 + 0];
                float v1 = lp[g * 4 + 1];
                float v2 = lp[g * 4 + 2];
                float v3 = lp[g * 4 + 3];
                float mx = fmaxf(fmaxf(v0, v1), fmaxf(v2, v3));
                if (mx > bv[9]) {
                    int gi = gibase + g * 4;
                    if (v0 > bv[9]) tk_insert_v(bv, bi, v0, gi);
                    if (v1 > bv[9]) tk_insert_v(bv, bi, v1, gi + 1);
                    if (v2 > bv[9]) tk_insert_v(bv, bi, v2, gi + 2);
                    if (v3 > bv[9]) tk_insert_v(bv, bi, v3, gi + 3);
                }
            }
        }
    }

    __syncthreads();  // all scans done; k0 dead -> overlay

    float* tv = (float*)(smraw + SM_K0);   // [32*4*10] floats (5120 B)
    int* ti = (int*)(tv + 1280);           // [32*4*10] ints   (5120 B)
    float* wv = (float*)(ti + 1280);       // [32*10]          (1280 B)
    int* wi = (int*)(wv + 320);            // [32*10]          (1280 B)

#pragma unroll
    for (int k = 0; k < 10; ++k) {
        tv[(row * 4 + sub) * 10 + k] = bv[k];
        ti[(row * 4 + sub) * 10 + k] = bi[k];
    }
    __syncthreads();

    // merge 4 partial lists per row -> sigmoid/softmax/threshold weights
    if (t < 32) {
        float fv[10];
        int fi[10];
#pragma unroll
        for (int k = 0; k < 10; ++k) { fv[k] = -1e30f; fi[k] = 0x7fffffff; }
        for (int s = 0; s < 4; ++s)
            for (int k = 0; k < 10; ++k) {
                float v = tv[(t * 4 + s) * 10 + k];
                int gi = ti[(t * 4 + s) * 10 + k];
                if (tk_better(v, gi, fv[9], fi[9])) tk_insert(fv, fi, v, gi);
            }
        float sig[10];
#pragma unroll
        for (int k = 0; k < 10; ++k) sig[k] = 1.f / (1.f + expf(-fv[k]));
        float e[10];
        float den = 0.f;
#pragma unroll
        for (int k = 0; k < 10; ++k) { e[k] = expf(sig[k] - sig[0]); den += e[k]; }
        float inv = 1.f / den;
#pragma unroll
        for (int k = 0; k < 10; ++k) {
            float w = e[k] * inv;
            if (!(sig[k] > THR_S)) w = 0.f;
            wv[t * 10 + k] = w;
            wi[t * 10 + k] = fi[k];
        }
    }
    __syncthreads();

    // sparse aggregation: rna gather (direct) + atac scatter (atomic)
    {
        int d = t & 63, g = t >> 6;
        for (int rr = g; rr < 32; rr += 2) {
            int rloc = rr >> 1, h = rr & 1;
            int r = r0 + rloc;
            float vr = g_VR[(size_t)r * 128 + h * 64 + d];
            float accO = 0.f;
#pragma unroll
            for (int k = 0; k < 10; ++k) {
                float w = wv[rr * 10 + k];
                int a = wi[rr * 10 + k];
                if (w != 0.f) {
                    accO += w * g_VA[(size_t)a * 128 + h * 64 + d];
                    atomicAdd(&g_AGGA[(size_t)a * 128 + h * 64 + d], w * vr);
                }
            }
            g_AGGR[(size_t)r * 128 + h * 64 + d] = accO;
        }
    }
}

// ---------------- launch ----------------
extern "C" void kernel_launch(void* const* d_in, const int* in_sizes, int n_in,
                              void* d_out, int out_size) {
    const float* x_rna = (const float*)d_in[0];
    const float* x_atac = (const float*)d_in[1];
    const float* chrom_mask = (const float*)d_in[2];
    const float* Wq = (const float*)d_in[3];
    const float* bq = (const float*)d_in[4];
    const float* Wk = (const float*)d_in[5];
    const float* bk = (const float*)d_in[6];
    const float* Wvr = (const float*)d_in[7];
    const float* bvr = (const float*)d_in[8];
    const float* Wva = (const float*)d_in[9];
    const float* bva = (const float*)d_in[10];
    const float* Wor = (const float*)d_in[11];
    const float* bor = (const float*)d_in[12];
    const float* Woa = (const float*)d_in[13];
    const float* boa = (const float*)d_in[14];
    const float* Wsr = (const float*)d_in[15];
    const float* bsr = (const float*)d_in[16];
    const float* Wsa = (const float*)d_in[17];
    const float* bsa = (const float*)d_in[18];
    const float* Wdr = (const float*)d_in[19];
    const float* bdr = (const float*)d_in[20];
    const float* Wda = (const float*)d_in[21];
    const float* bda = (const float*)d_in[22];
    float* out = (float*)d_out;

    float *Qp, *Kp, *VRp, *VAp, *AGGRp, *AGGAp, *CRp, *CAp;
    cudaGetSymbolAddress((void**)&Qp, g_Q);
    cudaGetSymbolAddress((void**)&Kp, g_K);
    cudaGetSymbolAddress((void**)&VRp, g_VR);
    cudaGetSymbolAddress((void**)&VAp, g_VA);
    cudaGetSymbolAddress((void**)&AGGRp, g_AGGR);
    cudaGetSymbolAddress((void**)&AGGAp, g_AGGA);
    cudaGetSymbolAddress((void**)&CRp, g_CR);
    cudaGetSymbolAddress((void**)&CAp, g_CA);

    cudaMemsetAsync(AGGAp, 0, (size_t)N_ATAC * HID * sizeof(float));

    GemmBatch b1 = {};
    b1.op[0] = {x_rna, Wq, bq, Qp, N_RNA, IN_C, 128, 0};
    b1.op[1] = {x_atac, Wk, bk, Kp, N_ATAC, IN_C, 128, 0};
    b1.op[2] = {x_rna, Wvr, bvr, VRp, N_RNA, IN_C, 128, 0};
    b1.op[3] = {x_atac, Wva, bva, VAp, N_ATAC, IN_C, 128, 0};
    b1.op[4] = {x_rna, Wsr, bsr, CRp, N_RNA, IN_C, 256, 128};
    b1.op[5] = {x_atac, Wsa, bsa, CAp, N_ATAC, IN_C, 256, 128};
    gemm_kernel<<<dim3(128, 6), 256>>>(b1);

    cudaFuncSetAttribute(attn_kernel, cudaFuncAttributeMaxDynamicSharedMemorySize, SM_TOTAL);
    attn_kernel<<<N_RNA / 16, 128, SM_TOTAL>>>(chrom_mask);

    GemmBatch b2 = {};
    b2.op[0] = {AGGRp, Wor, bor, CRp, N_RNA, HID, 256, 0};
    b2.op[1] = {AGGAp, Woa, boa, CAp, N_ATAC, HID, 256, 0};
    gemm_kernel<<<dim3(128, 2), 256>>>(b2);

    GemmBatch b3 = {};
    b3.op[0] = {CRp, Wdr, bdr, out, N_RNA, 2 * HID, 128, 0};
    b3.op[1] = {CAp, Wda, bda, out + (size_t)N_RNA * HID, N_ATAC, 2 * HID, 128, 0};
    gemm_kernel<<<dim3(128, 2), 256>>>(b3);
}